// round 1
// baseline (speedup 1.0000x reference)
#include <cuda_runtime.h>

// Problem constants (fixed by the reference)
#define BQ 512
#define TQ 8192
#define KW 5
#define CE 512              // emitted timesteps per chunk
#define CW 512              // warm-up timesteps (speculative convergence window)
#define NC (TQ / CE)        // 16 chunks
#define K1_BLOCK 64

// One LIF step for all 3 channels, producing the (unnormalized) saliency.
// Uses explicit rn mul/add (no FMA contraction) to match the reference arithmetic.
#define STEP1(x0, x1, x2, OUT)                                              \
    {                                                                       \
        v0 = __fadd_rn(__fmul_rn(d0, v0), (x0));                            \
        v1 = __fadd_rn(__fmul_rn(d1, v1), (x1));                            \
        v2 = __fadd_rn(__fmul_rn(d2, v2), (x2));                            \
        float s0 = (v0 >= 1.0f) ? 1.0f : 0.0f;                              \
        float s1 = (v1 >= 1.0f) ? 1.0f : 0.0f;                              \
        float s2 = (v2 >= 1.0f) ? 1.0f : 0.0f;                              \
        v0 = __fadd_rn(v0, -s0);                                            \
        v1 = __fadd_rn(v1, -s1);                                            \
        v2 = __fadd_rn(v2, -s2);                                            \
        (OUT) = __fadd_rn(__fadd_rn(__fmul_rn(w0, s0), __fmul_rn(w1, s1)),  \
                          __fmul_rn(w2, s2));                               \
    }

__global__ __launch_bounds__(K1_BLOCK)
void k1_scan(const float* __restrict__ amp, const float* __restrict__ pitch,
             const float* __restrict__ bnd, const float* __restrict__ decay,
             const float* __restrict__ wts, float* __restrict__ salraw)
{
    int s = blockIdx.x * K1_BLOCK + threadIdx.x;   // 0 .. BQ*NC-1
    int b = s >> 4;                                 // s / NC
    int c = s & (NC - 1);                           // s % NC

    const float d0 = __ldg(decay + 0);
    const float d1 = __ldg(decay + 1);
    const float d2 = __ldg(decay + 2);
    const float w0 = __ldg(wts + 0);
    const float w1 = __ldg(wts + 1);
    const float w2 = __ldg(wts + 2);

    const float* pa = amp   + (size_t)b * TQ;
    const float* pp = pitch + (size_t)b * TQ;
    const float* pb = bnd   + (size_t)b * TQ;
    float*       po = salraw + (size_t)b * TQ;

    const int t_emit = c * CE;
    // Chunk 0 warms on [0, CW) just to keep warp-uniform loop counts, then
    // resets state (its true initial state v=0 is exact).
    const int tw = (c == 0) ? 0 : (t_emit - CW);

    float v0 = 0.f, v1 = 0.f, v2 = 0.f;

    // ---- warm-up: converge the speculative state (no stores) ----
    #pragma unroll 1
    for (int i = 0; i < CW; i += 8) {
        const float* qa = pa + tw + i;
        const float* qp = pp + tw + i;
        const float* qb = pb + tw + i;
        float4 a0 = *(const float4*)(qa);
        float4 a1 = *(const float4*)(qa + 4);
        float4 p0 = *(const float4*)(qp);
        float4 p1 = *(const float4*)(qp + 4);
        float4 c0 = *(const float4*)(qb);
        float4 c1 = *(const float4*)(qb + 4);
        float dump;
        STEP1(a0.x, p0.x, c0.x, dump); (void)dump;
        STEP1(a0.y, p0.y, c0.y, dump); (void)dump;
        STEP1(a0.z, p0.z, c0.z, dump); (void)dump;
        STEP1(a0.w, p0.w, c0.w, dump); (void)dump;
        STEP1(a1.x, p1.x, c1.x, dump); (void)dump;
        STEP1(a1.y, p1.y, c1.y, dump); (void)dump;
        STEP1(a1.z, p1.z, c1.z, dump); (void)dump;
        STEP1(a1.w, p1.w, c1.w, dump); (void)dump;
    }
    if (c == 0) { v0 = 0.f; v1 = 0.f; v2 = 0.f; }

    // ---- emit: run the chunk and store raw saliency ----
    #pragma unroll 1
    for (int i = 0; i < CE; i += 8) {
        const float* qa = pa + t_emit + i;
        const float* qp = pp + t_emit + i;
        const float* qb = pb + t_emit + i;
        float4 a0 = *(const float4*)(qa);
        float4 a1 = *(const float4*)(qa + 4);
        float4 p0 = *(const float4*)(qp);
        float4 p1 = *(const float4*)(qp + 4);
        float4 c0 = *(const float4*)(qb);
        float4 c1 = *(const float4*)(qb + 4);
        float4 o0, o1;
        STEP1(a0.x, p0.x, c0.x, o0.x);
        STEP1(a0.y, p0.y, c0.y, o0.y);
        STEP1(a0.z, p0.z, c0.z, o0.z);
        STEP1(a0.w, p0.w, c0.w, o0.w);
        STEP1(a1.x, p1.x, c1.x, o1.x);
        STEP1(a1.y, p1.y, c1.y, o1.y);
        STEP1(a1.z, p1.z, c1.z, o1.z);
        STEP1(a1.w, p1.w, c1.w, o1.w);
        *(float4*)(po + t_emit + i)     = o0;
        *(float4*)(po + t_emit + i + 4) = o1;
    }
}

// Per-row: max, top-5 (tie -> lowest index, matching jax.lax.top_k),
// normalize sal in-place, write mu and indices.
__global__ __launch_bounds__(256)
void k2_finish(float* __restrict__ out)
{
    __shared__ float vals[TQ];                    // 32 KB
    __shared__ unsigned long long redbuf[8];
    __shared__ int   winidx[KW];
    __shared__ float winval[KW];

    const int b   = blockIdx.x;
    const int tid = threadIdx.x;
    float* sal = out + BQ + (size_t)b * TQ;

    for (int i = tid; i < TQ / 4; i += 256) {
        float4 x = ((const float4*)sal)[i];
        vals[4 * i + 0] = x.x;
        vals[4 * i + 1] = x.y;
        vals[4 * i + 2] = x.z;
        vals[4 * i + 3] = x.w;
    }
    __syncthreads();

    // 5 argmax passes; key = (order-mapped value, 8191 - idx) so ties pick
    // the lowest index, exactly like jax.lax.top_k.
    for (int k = 0; k < KW; k++) {
        unsigned long long best = 0ull;
        for (int i = tid; i < TQ; i += 256) {
            unsigned m = __float_as_uint(vals[i]) ^ 0x80000000u; // vals >= 0 or the -1 marker
            unsigned long long key =
                ((unsigned long long)m << 32) | (unsigned)(TQ - 1 - i);
            if (key > best) best = key;
        }
        #pragma unroll
        for (int off = 16; off; off >>= 1) {
            unsigned long long o = __shfl_xor_sync(0xffffffffu, best, off);
            if (o > best) best = o;
        }
        if ((tid & 31) == 0) redbuf[tid >> 5] = best;
        __syncthreads();
        if (tid == 0) {
            unsigned long long bb = redbuf[0];
            #pragma unroll
            for (int wgi = 1; wgi < 8; wgi++)
                if (redbuf[wgi] > bb) bb = redbuf[wgi];
            int idx = TQ - 1 - (int)(bb & 0xffffffffu);
            winidx[k] = idx;
            winval[k] = vals[idx];
            vals[idx] = -1.0f;                    // exclude from later passes
        }
        __syncthreads();
    }

    // restore winners before the normalization pass
    if (tid < KW) vals[winidx[tid]] = winval[tid];
    __syncthreads();

    const float recip = 1.0f / (winval[0] + 1e-6f);   // winval[0] == row max
    for (int i = tid; i < TQ / 4; i += 256) {
        float4 x;
        x.x = vals[4 * i + 0] * recip;
        x.y = vals[4 * i + 1] * recip;
        x.z = vals[4 * i + 2] * recip;
        x.w = vals[4 * i + 3] * recip;
        ((float4*)sal)[i] = x;
    }

    if (tid == 0) {
        float acc = 0.f;
        #pragma unroll
        for (int k = 0; k < KW; k++) acc += winval[k] * recip;
        float avg = acc / 5.0f;
        float mu  = 0.5f + 2.0f * tanhf(1.8f * avg);
        out[b] = mu;
        float* oi = out + BQ + (size_t)BQ * TQ + (size_t)b * KW;
        #pragma unroll
        for (int k = 0; k < KW; k++) oi[k] = (float)winidx[k];
    }
}

extern "C" void kernel_launch(void* const* d_in, const int* in_sizes, int n_in,
                              void* d_out, int out_size)
{
    const float* amp   = (const float*)d_in[0];
    const float* pitch = (const float*)d_in[1];
    const float* bnd   = (const float*)d_in[2];
    const float* decay = (const float*)d_in[3];
    const float* wts   = (const float*)d_in[4];
    float* out = (float*)d_out;

    float* salraw = out + BQ;   // raw saliency staged in the output's sal region

    k1_scan<<<(BQ * NC) / K1_BLOCK, K1_BLOCK>>>(amp, pitch, bnd, decay, wts, salraw);
    k2_finish<<<BQ, 256>>>(out);
}

// round 2
// speedup vs baseline: 2.2106x; 2.2106x over previous
#include <cuda_runtime.h>
#include <math.h>

// Problem constants
#define BQ 512
#define TQ 8192
#define KW 5

// Chunked-speculative scan parameters
#define CE 256              // emitted steps per chunk
#define CW 224              // warm-up steps (contraction 0.7^224, chunk 0 exact)
#define W  32               // tile width (steps per staged tile)
#define NT ((CW + CE) / W)  // 15 tiles
#define ET (CW / W)         // 7 = first emitting tile
#define ROWS 4              // rows (batches) per block; 32 chunks per row
#define PIN 36              // smem input pitch (words) per chunk slice: 16B aligned + conflict-free
#define SROW 8224           // padded sal row: f(t) = t + t/256, max 8222
#define IN_WORDS (ROWS * 3 * 32 * PIN)   // 13824
#define SAL_WORDS (ROWS * SROW)          // 32896
#define SMEM_BYTES ((IN_WORDS + SAL_WORDS) * 4)  // 186880 B

// One LIF step, all 3 channels. Explicit rn mul/add (no FMA contraction) to
// match the reference arithmetic bit-for-bit (validated rel_err 0.0).
#define STEP1(x0, x1, x2, OUT)                                              \
    {                                                                       \
        v0 = __fadd_rn(__fmul_rn(d0, v0), (x0));                            \
        v1 = __fadd_rn(__fmul_rn(d1, v1), (x1));                            \
        v2 = __fadd_rn(__fmul_rn(d2, v2), (x2));                            \
        float s0_ = (v0 >= 1.0f) ? 1.0f : 0.0f;                             \
        float s1_ = (v1 >= 1.0f) ? 1.0f : 0.0f;                             \
        float s2_ = (v2 >= 1.0f) ? 1.0f : 0.0f;                             \
        v0 = __fadd_rn(v0, -s0_);                                           \
        v1 = __fadd_rn(v1, -s1_);                                           \
        v2 = __fadd_rn(v2, -s2_);                                           \
        (OUT) = __fadd_rn(__fadd_rn(__fmul_rn(w0, s0_), __fmul_rn(w1, s1_)),\
                          __fmul_rn(w2, s2_));                              \
    }

// Coalesced tile load: warp r loads its row's 32 slices x 32 steps x 3 channels.
// Lane l covers chunk (4i + l/8), floats ((l&7)*4 .. +3) of the slice.
#define LDG_TILE(J)                                                         \
    do {                                                                    \
        const int base_t = (J) * W - CW;                                    \
        _Pragma("unroll")                                                   \
        for (int i = 0; i < 8; i++) {                                       \
            int ch_c = (i << 2) + sub;                                      \
            long g0 = (long)ch_c * CE + base_t;                             \
            if (g0 < 0) g0 = 0;  /* chunk 0 warm: garbage, reset later */   \
            rb0[i] = *(const float4*)(pr0 + g0 + off);                      \
            rb1[i] = *(const float4*)(pr1 + g0 + off);                      \
            rb2[i] = *(const float4*)(pr2 + g0 + off);                      \
        }                                                                   \
    } while (0)

#define STS_TILE()                                                          \
    do {                                                                    \
        _Pragma("unroll")                                                   \
        for (int i = 0; i < 8; i++) {                                       \
            int ch_c = (i << 2) + sub;                                      \
            *(float4*)&sin_[((r * 3 + 0) * 32 + ch_c) * PIN + off] = rb0[i];\
            *(float4*)&sin_[((r * 3 + 1) * 32 + ch_c) * PIN + off] = rb1[i];\
            *(float4*)&sin_[((r * 3 + 2) * 32 + ch_c) * PIN + off] = rb2[i];\
        }                                                                   \
    } while (0)

__global__ __launch_bounds__(ROWS * 32, 1)
void fused_spike_kernel(const float* __restrict__ amp,
                        const float* __restrict__ pitch,
                        const float* __restrict__ bnd,
                        const float* __restrict__ decay,
                        const float* __restrict__ wts,
                        float* __restrict__ out)
{
    extern __shared__ float sm[];
    float* sin_ = sm;               // staged input tiles
    float* ssal = sm + IN_WORDS;    // padded full sal rows

    const int lane = threadIdx.x & 31;
    const int r    = threadIdx.x >> 5;        // warp = row within block
    const int c    = lane;                     // chunk within row
    const int b    = blockIdx.x * ROWS + r;    // global row

    const float d0 = decay[0], d1 = decay[1], d2 = decay[2];
    const float w0 = wts[0],   w1 = wts[1],   w2 = wts[2];

    const float* pr0 = amp   + (size_t)b * TQ;
    const float* pr1 = pitch + (size_t)b * TQ;
    const float* pr2 = bnd   + (size_t)b * TQ;

    const int sub = lane >> 3;           // slice group 0..3
    const int off = (lane & 7) << 2;     // float offset within slice

    float4 rb0[8], rb1[8], rb2[8];

    float v0 = 0.f, v1 = 0.f, v2 = 0.f;

    LDG_TILE(0);

    #pragma unroll 1
    for (int j = 0; j < NT; j++) {
        STS_TILE();
        __syncthreads();
        if (j + 1 < NT) LDG_TILE(j + 1);   // prefetch overlaps compute

        if (j == ET && c == 0) { v0 = 0.f; v1 = 0.f; v2 = 0.f; }  // chunk 0 exact

        const int b0 = ((r * 3 + 0) * 32 + c) * PIN;
        const int b1 = ((r * 3 + 1) * 32 + c) * PIN;
        const int b2 = ((r * 3 + 2) * 32 + c) * PIN;

        if (j >= ET) {
            // emit: write sal into padded smem row, addr = 257c + 32*(j-ET) + t
            float* sd = ssal + r * SROW + c * 257 + (j - ET) * 32;
            #pragma unroll
            for (int t = 0; t < W; t += 4) {
                float4 xa = *(const float4*)&sin_[b0 + t];
                float4 xp = *(const float4*)&sin_[b1 + t];
                float4 xb = *(const float4*)&sin_[b2 + t];
                float o;
                STEP1(xa.x, xp.x, xb.x, o); sd[t + 0] = o;
                STEP1(xa.y, xp.y, xb.y, o); sd[t + 1] = o;
                STEP1(xa.z, xp.z, xb.z, o); sd[t + 2] = o;
                STEP1(xa.w, xp.w, xb.w, o); sd[t + 3] = o;
            }
        } else {
            // warm-up: converge only
            #pragma unroll
            for (int t = 0; t < W; t += 4) {
                float4 xa = *(const float4*)&sin_[b0 + t];
                float4 xp = *(const float4*)&sin_[b1 + t];
                float4 xb = *(const float4*)&sin_[b2 + t];
                float o;
                STEP1(xa.x, xp.x, xb.x, o);
                STEP1(xa.y, xp.y, xb.y, o);
                STEP1(xa.z, xp.z, xb.z, o);
                STEP1(xa.w, xp.w, xb.w, o);
                (void)o;
            }
        }
        __syncthreads();
    }

    // ---------------- per-warp epilogue: top-5, max, normalize, mu ----------
    const float* srow = ssal + r * SROW;

    // per-lane top-5 over lane-strided elements; key = (valbits<<32)|(8191-t)
    // replicates jax.lax.top_k value-then-lowest-index ordering exactly.
    unsigned long long s0 = 0, s1 = 0, s2 = 0, s3 = 0, s4 = 0;
    #pragma unroll 4
    for (int q = 0; q < 256; q++) {
        float v = srow[(q << 5) + lane + (q >> 3)];
        unsigned long long key =
            ((unsigned long long)__float_as_uint(v) << 32)
            | (unsigned)(TQ - 1 - ((q << 5) + lane));
        if (key > s4) {
            s4 = key;
            if (s4 > s3) { unsigned long long t_ = s3; s3 = s4; s4 = t_; }
            if (s3 > s2) { unsigned long long t_ = s2; s2 = s3; s3 = t_; }
            if (s2 > s1) { unsigned long long t_ = s1; s1 = s2; s2 = t_; }
            if (s1 > s0) { unsigned long long t_ = s0; s0 = s1; s1 = t_; }
        }
    }

    // merge 32 sorted lists: 5 rounds of warp-max with owner pop (keys unique)
    int p = 0;
    unsigned long long win[KW];
    #pragma unroll
    for (int k = 0; k < KW; k++) {
        unsigned long long cand =
            (p == 0) ? s0 : (p == 1) ? s1 : (p == 2) ? s2 :
            (p == 3) ? s3 : (p == 4) ? s4 : 0ull;
        unsigned long long m = cand;
        #pragma unroll
        for (int o = 16; o; o >>= 1) {
            unsigned long long x = __shfl_xor_sync(0xffffffffu, m, o);
            if (x > m) m = x;
        }
        if (cand == m) p++;
        win[k] = m;
    }

    const float maxv  = __uint_as_float((unsigned)(win[0] >> 32));
    const float recip = 1.0f / (maxv + 1e-6f);

    // normalized sal: coalesced stores
    float* go = out + BQ + (size_t)b * TQ;
    #pragma unroll 4
    for (int q = 0; q < 256; q++) {
        go[(q << 5) + lane] = srow[(q << 5) + lane + (q >> 3)] * recip;
    }

    if (lane == 0) {
        float acc = 0.f;
        #pragma unroll
        for (int k = 0; k < KW; k++)
            acc += __uint_as_float((unsigned)(win[k] >> 32)) * recip;
        float avg = acc / 5.0f;
        out[b] = 0.5f + 2.0f * tanhf(1.8f * avg);
        float* oi = out + BQ + (size_t)BQ * TQ + (size_t)b * KW;
        #pragma unroll
        for (int k = 0; k < KW; k++)
            oi[k] = (float)(TQ - 1 - (int)(unsigned)(win[k] & 0xffffffffu));
    }
}

extern "C" void kernel_launch(void* const* d_in, const int* in_sizes, int n_in,
                              void* d_out, int out_size)
{
    const float* amp   = (const float*)d_in[0];
    const float* pitch = (const float*)d_in[1];
    const float* bnd   = (const float*)d_in[2];
    const float* decay = (const float*)d_in[3];
    const float* wts   = (const float*)d_in[4];
    float* out = (float*)d_out;

    cudaFuncSetAttribute(fused_spike_kernel,
                         cudaFuncAttributeMaxDynamicSharedMemorySize,
                         SMEM_BYTES);

    fused_spike_kernel<<<BQ / ROWS, ROWS * 32, SMEM_BYTES>>>(
        amp, pitch, bnd, decay, wts, out);
}